// round 11
// baseline (speedup 1.0000x reference)
#include <cuda_runtime.h>
#include <cuda_fp16.h>

#define D 64
#define L 64
#define BB 8
#define MAT (D*D)          // 4096 elems per matrix
#define NMAT (BB*L)        // 512 matrices
#define PAH 72             // fp16 A pitch (halves): 144B rows, conflict-free
#define PBT 72             // fp16 B-transposed pitch (halves): 16B-aligned rows

// All matrices in reciprocal-exp domain: W = exp(-m), stored fp16 normalized
// per-quarter (max=1) with float scales. log-semiring matmul:
//   out[i,j] = rcp( sum_k rcp( A[i,k] + B[k,j] ) )   (scale-homogeneous)
__device__ float g_p0tab[MAT];         // exp(-p[0]) fp32 (final)

// fp16 normalized storage (+ per-quarter float4 scales)
__device__ uint4 h_buf0_[NMAT * MAT / 8];
__device__ uint4 h_buf1_[NMAT * MAT / 8];
__device__ uint4 h_qtab_[256 * MAT / 8];
__device__ uint4 h_ttab_[16 * MAT / 8];
__device__ uint4 h_wtab_[4 * MAT / 8];
__device__ float4 g_sc0[NMAT];
__device__ float4 g_sc1[NMAT];
__device__ float4 g_scq[256];
__device__ float4 g_sct[16];
__device__ float4 g_scw[4];
#define H_BUF0 ((__half*)h_buf0_)
#define H_BUF1 ((__half*)h_buf1_)
#define H_QTAB ((__half*)h_qtab_)
#define H_TTAB ((__half*)h_ttab_)
#define H_WTAB ((__half*)h_wtab_)

__device__ __forceinline__ float frcp(float x) {
    float r;
    asm("rcp.approx.f32 %0, %1;" : "=f"(r) : "f"(x));
    return r;
}

__device__ __forceinline__ float sc_comp(float4 s, int q) {
    return (q < 2) ? (q == 0 ? s.x : s.y) : (q == 2 ? s.z : s.w);
}

// ---------------------------------------------------------------------------
// fp16 quarter matmul, k-paired half2 layout, fused normalize epilogue.
// One CTA = 64x16 output quarter q. Thread t: row = t>>2, owns cols
// {cg, cg+4, cg+8, cg+12} of the quarter (cg = t&3).
// A staged row-major (k-contiguous pairs); B staged TRANSPOSED sBt[j][k].
// ---------------------------------------------------------------------------
__device__ __forceinline__ void hmm_quarter(const __half* __restrict__ Ah, float4 scA,
                                            const __half* __restrict__ Bh, float scB,
                                            __half* __restrict__ Dst,
                                            float* __restrict__ scOut, int q) {
    __shared__ __align__(16) __half sA[D * PAH];
    __shared__ __align__(16) __half sBt[16 * PBT];
    __shared__ float wred[8];
    const int t = threadIdx.x;

    float s = fmaxf(fmaxf(fmaxf(scA.x, scA.y), fmaxf(scA.z, scA.w)), scB);
    float invs = 1.f / s;
    __half2 rB = __float2half2_rn(scB * invs);
    float rAf0 = scA.x * invs, rAf1 = scA.y * invs;
    float rAf2 = scA.z * invs, rAf3 = scA.w * invs;

    // stage A: 512 uint4 (8 halves each); column quarter of A = (c8>>1)
#pragma unroll
    for (int i = 0; i < 2; i++) {
        int id = t + i * 256;
        int r = id >> 3, c8 = id & 7;
        int qa = c8 >> 1;
        float rf = (qa < 2) ? (qa == 0 ? rAf0 : rAf1) : (qa == 2 ? rAf2 : rAf3);
        __half2 rA = __float2half2_rn(rf);
        uint4 v = ((const uint4*)Ah)[id];
        __half2* hv = (__half2*)&v;
        hv[0] = __hmul2(hv[0], rA); hv[1] = __hmul2(hv[1], rA);
        hv[2] = __hmul2(hv[2], rA); hv[3] = __hmul2(hv[3], rA);
        *(uint4*)&sA[r * PAH + c8 * 8] = v;
    }
    // stage B quarter TRANSPOSED: thread reads 4 consecutive j at one k,
    // scatters into sBt[j][k].
    {
        int k = t >> 2, j4 = (t & 3) * 4;
        uint2 v = *(const uint2*)&Bh[k * D + q * 16 + j4];
        __half2* hv = (__half2*)&v;
        hv[0] = __hmul2(hv[0], rB);
        hv[1] = __hmul2(hv[1], rB);
        const __half* hs = (const __half*)&v;
#pragma unroll
        for (int jj = 0; jj < 4; jj++)
            sBt[(j4 + jj) * PBT + k] = hs[jj];
    }
    __syncthreads();

    const int row = t >> 2, cg = t & 3;
    const __half* ap = &sA[row * PAH];
    const __half* bp0 = &sBt[(cg     ) * PBT];
    const __half* bp1 = &sBt[(cg +  4) * PBT];
    const __half* bp2 = &sBt[(cg +  8) * PBT];
    const __half* bp3 = &sBt[(cg + 12) * PBT];
    const __half2 hz = __float2half2_rn(0.f);
    __half2 acc0a = hz, acc0b = hz, acc1a = hz, acc1b = hz;
    __half2 acc2a = hz, acc2b = hz, acc3a = hz, acc3b = hz;

#pragma unroll
    for (int k8 = 0; k8 < 8; k8++) {
        uint4 a8 = *(const uint4*)&ap[k8 * 8];
        uint4 u0 = *(const uint4*)&bp0[k8 * 8];
        uint4 u1 = *(const uint4*)&bp1[k8 * 8];
        uint4 u2 = *(const uint4*)&bp2[k8 * 8];
        uint4 u3 = *(const uint4*)&bp3[k8 * 8];
        const __half2* ah = (const __half2*)&a8;
        const __half2* b0 = (const __half2*)&u0;
        const __half2* b1 = (const __half2*)&u1;
        const __half2* b2 = (const __half2*)&u2;
        const __half2* b3 = (const __half2*)&u3;
#pragma unroll
        for (int p = 0; p < 4; p += 2) {
            acc0a = __hadd2(acc0a, h2rcp(__hadd2(ah[p], b0[p])));
            acc1a = __hadd2(acc1a, h2rcp(__hadd2(ah[p], b1[p])));
            acc2a = __hadd2(acc2a, h2rcp(__hadd2(ah[p], b2[p])));
            acc3a = __hadd2(acc3a, h2rcp(__hadd2(ah[p], b3[p])));
            acc0b = __hadd2(acc0b, h2rcp(__hadd2(ah[p + 1], b0[p + 1])));
            acc1b = __hadd2(acc1b, h2rcp(__hadd2(ah[p + 1], b1[p + 1])));
            acc2b = __hadd2(acc2b, h2rcp(__hadd2(ah[p + 1], b2[p + 1])));
            acc3b = __hadd2(acc3b, h2rcp(__hadd2(ah[p + 1], b3[p + 1])));
        }
    }

    // merge partials in fp32, final rcp
    float o0, o1, o2, o3;
    {
        float2 f0 = __half22float2(acc0a), g0 = __half22float2(acc0b);
        float2 f1 = __half22float2(acc1a), g1 = __half22float2(acc1b);
        float2 f2 = __half22float2(acc2a), g2 = __half22float2(acc2b);
        float2 f3 = __half22float2(acc3a), g3 = __half22float2(acc3b);
        o0 = frcp((f0.x + f0.y) + (g0.x + g0.y));
        o1 = frcp((f1.x + f1.y) + (g1.x + g1.y));
        o2 = frcp((f2.x + f2.y) + (g2.x + g2.y));
        o3 = frcp((f3.x + f3.y) + (g3.x + g3.y));
    }

    // fused per-quarter max reduction + normalized fp16 store
    float m = fmaxf(fmaxf(o0, o1), fmaxf(o2, o3));
#pragma unroll
    for (int off = 16; off; off >>= 1)
        m = fmaxf(m, __shfl_xor_sync(0xffffffffu, m, off));
    if ((t & 31) == 0) wred[t >> 5] = m;
    __syncthreads();
    float mx = wred[0];
#pragma unroll
    for (int i = 1; i < 8; i++) mx = fmaxf(mx, wred[i]);
    float inv = (mx > 0.f) ? frcp(mx) : 0.f;

    __half* drow = &Dst[row * D + q * 16 + cg];
    drow[0]  = __float2half_rn(o0 * inv);
    drow[4]  = __float2half_rn(o1 * inv);
    drow[8]  = __float2half_rn(o2 * inv);
    drow[12] = __float2half_rn(o3 * inv);
    if (t == 0) *scOut = s * mx;
}

// ---------------------------------------------------------------------------
// Resolver: value of index m before pass 2^slog lives at level
// p = min(floor(log2 m), slog-1).
// ---------------------------------------------------------------------------
struct HMat { const __half* m; float4 sc; };

__device__ __forceinline__ int quad_idx(const int* __restrict__ act, int b, int m) {
    const int* a = act + b * L + (m - 3);
    return ((a[0] * 4 + a[1]) * 4 + a[2]) * 4 + a[3];
}

__device__ __forceinline__ HMat latest_h(const int* __restrict__ act,
                                         int b, int m, int slog) {
    int slot = b * L + m;
    size_t off = (size_t)slot * MAT;
    HMat r;
    if (m < 2) { r.m = H_BUF0 + off; r.sc = g_sc0[slot]; return r; }
    int p = 31 - __clz(m);
    if (p > slog - 1) p = slog - 1;
    if (p == 1) {
        if (m == 2) { r.m = H_BUF1 + off; r.sc = g_sc1[slot]; return r; }
        int idx = quad_idx(act, b, m);
        r.m = H_QTAB + (size_t)idx * MAT; r.sc = g_scq[idx]; return r;
    }
    if (p & 1) { r.m = H_BUF1 + off; r.sc = g_sc1[slot]; }
    else       { r.m = H_BUF0 + off; r.sc = g_sc0[slot]; }
    return r;
}

// ---------------------------------------------------------------------------
// exp tables: a==0 -> p0tab fp32. a>=1 -> wtab fp16 normalized + scale.
// ---------------------------------------------------------------------------
__global__ void exp_tab_kernel(const float* __restrict__ p) {
    int a = blockIdx.x;
    __shared__ float wred[8];
    int t = threadIdx.x;  // 256
    const float4* src = (const float4*)(p + (size_t)a * MAT);
    float4 v[4];
    float m = 0.f;
#pragma unroll
    for (int i = 0; i < 4; i++) {
        float4 x = src[t + i * 256];
        v[i] = make_float4(expf(-x.x), expf(-x.y), expf(-x.z), expf(-x.w));
        m = fmaxf(m, fmaxf(fmaxf(v[i].x, v[i].y), fmaxf(v[i].z, v[i].w)));
    }
    if (a == 0) {
#pragma unroll
        for (int i = 0; i < 4; i++) ((float4*)g_p0tab)[t + i * 256] = v[i];
        return;
    }
#pragma unroll
    for (int off = 16; off; off >>= 1)
        m = fmaxf(m, __shfl_xor_sync(0xffffffffu, m, off));
    if ((t & 31) == 0) wred[t >> 5] = m;
    __syncthreads();
    float mx = wred[0];
#pragma unroll
    for (int i = 1; i < 8; i++) mx = fmaxf(mx, wred[i]);
    float inv = (mx > 0.f) ? 1.f / mx : 0.f;
    __half* hdst = H_WTAB + (size_t)(a - 1) * MAT;
#pragma unroll
    for (int i = 0; i < 4; i++) {
        __half2 h0 = __floats2half2_rn(v[i].x * inv, v[i].y * inv);
        __half2 h1 = __floats2half2_rn(v[i].z * inv, v[i].w * inv);
        uint2 u; u.x = *(unsigned*)&h0; u.y = *(unsigned*)&h1;
        ((uint2*)hdst)[t + i * 256] = u;
    }
    if (t == 0) g_scw[a - 1] = make_float4(mx, mx, mx, mx);
}

// pair products fp16: 16 pairs x 4 quarters = 64 CTAs
__global__ void __launch_bounds__(256, 5) pairh_kernel() {
    int pidx = blockIdx.x >> 2, q = blockIdx.x & 3;
    int a = pidx >> 2, b = pidx & 3;
    hmm_quarter(H_WTAB + (size_t)a * MAT, g_scw[a],
                H_WTAB + (size_t)b * MAT, sc_comp(g_scw[b], q),
                H_TTAB + (size_t)pidx * MAT, (float*)&g_sct[pidx] + q, q);
}

// quads (1024) + tris (32) + base fp16 copies l=0,1 (16) = 1072 CTAs
__global__ void __launch_bounds__(256, 5) stage2h_kernel(const int* __restrict__ act) {
    int bid = blockIdx.x;
    if (bid < 1024) {
        int qidx = bid >> 2, q = bid & 3;
        int hi = qidx >> 4, lo = qidx & 15;
        hmm_quarter(H_TTAB + (size_t)hi * MAT, g_sct[hi],
                    H_TTAB + (size_t)lo * MAT, sc_comp(g_sct[lo], q),
                    H_QTAB + (size_t)qidx * MAT, (float*)&g_scq[qidx] + q, q);
    } else if (bid < 1056) {
        int i = bid - 1024;
        int b = i >> 2, q = i & 3;
        int a0 = act[b * L], a12 = act[b * L + 1] * 4 + act[b * L + 2];
        int slot = b * L + 2;
        hmm_quarter(H_WTAB + (size_t)a0 * MAT, g_scw[a0],
                    H_TTAB + (size_t)a12 * MAT, sc_comp(g_sct[a12], q),
                    H_BUF1 + (size_t)slot * MAT, (float*)&g_sc1[slot] + q, q);
    } else {
        int i = bid - 1056;                 // 0..15
        int b = i >> 1, which = i & 1;      // l = 0 or 1
        int slot = b * L + which;
        const uint4* src;
        float4 sc;
        if (which) {
            int pidx = act[b * L] * 4 + act[b * L + 1];
            src = (const uint4*)(H_TTAB + (size_t)pidx * MAT);
            sc = g_sct[pidx];
        } else {
            int a0 = act[b * L];
            src = (const uint4*)(H_WTAB + (size_t)a0 * MAT);
            sc = g_scw[a0];
        }
        uint4* dst = (uint4*)(H_BUF0 + (size_t)slot * MAT);
        for (int j = threadIdx.x; j < MAT / 8; j += 256) dst[j] = src[j];
        if (threadIdx.x == 0) g_sc0[slot] = sc;
    }
}

// Doubling pass for step = 2^slog (slog >= 2). Fully fp16, fused normalize.
__global__ void __launch_bounds__(256, 5) hstep_kernel(const int* __restrict__ act,
                                                       int slog) {
    int step = 1 << slog, n = L - step;
    int idx = blockIdx.x >> 2, q = blockIdx.x & 3;
    int b = idx / n;
    int l = step + (idx - b * n);
    HMat A = latest_h(act, b, l - step, slog);
    HMat Bm = latest_h(act, b, l, slog);
    int slot = b * L + l;
    __half* dst = ((slog & 1) ? H_BUF1 : H_BUF0) + (size_t)slot * MAT;
    float* scarr = (float*)(((slog & 1) ? g_sc1 : g_sc0) + slot) + q;
    hmm_quarter(A.m, A.sc, Bm.m, sc_comp(Bm.sc, q), dst, scarr, q);
}

// Final: x = init (x) PM ; y = x (x) p0 ; output in log domain.
__global__ void final_kernel(const int* __restrict__ act,
                             const float* __restrict__ init_vec,
                             float* __restrict__ out) {
    int bl = blockIdx.x;
    int b = bl >> 6, l = bl & 63;
    HMat W = latest_h(act, b, l, 6);
    __shared__ float ci[D];
    __shared__ float xw[D];
    int t = threadIdx.x;   // 64
    ci[t] = expf(-init_vec[t]);
    __syncthreads();

    float scq = sc_comp(W.sc, t >> 4);
    float s = 0.f;
#pragma unroll 8
    for (int k = 0; k < D; k++)
        s += frcp(fmaf(scq, __half2float(W.m[k * D + t]), ci[k]));
    xw[t] = frcp(s);
    __syncthreads();

    float s2 = 0.f;
#pragma unroll 8
    for (int k = 0; k < D; k++)
        s2 += frcp(xw[k] + g_p0tab[k * D + t]);
    out[(size_t)bl * D + t] = logf(s2);
}

extern "C" void kernel_launch(void* const* d_in, const int* in_sizes, int n_in,
                              void* d_out, int out_size) {
    const float* p        = (const float*)d_in[0];  // (5, 64, 64)
    const float* init_vec = (const float*)d_in[1];  // (64,)
    const int*   act      = (const int*)d_in[2];    // (8, 64)
    float* out = (float*)d_out;                     // (8, 64, 64)

    exp_tab_kernel<<<5, 256>>>(p);
    pairh_kernel<<<64, 256>>>();
    stage2h_kernel<<<1072, 256>>>(act);
    hstep_kernel<<<8 * (L - 4)  * 4, 256>>>(act, 2);   // -> H_BUF0
    hstep_kernel<<<8 * (L - 8)  * 4, 256>>>(act, 3);   // -> H_BUF1
    hstep_kernel<<<8 * (L - 16) * 4, 256>>>(act, 4);   // -> H_BUF0
    hstep_kernel<<<8 * (L - 32) * 4, 256>>>(act, 5);   // -> H_BUF1
    final_kernel<<<512, 64>>>(act, init_vec, out);
}

// round 12
// speedup vs baseline: 1.1935x; 1.1935x over previous
#include <cuda_runtime.h>
#include <cuda_fp16.h>

#define D 64
#define L 64
#define BB 8
#define MAT (D*D)          // 4096 elems per matrix
#define NMAT (BB*L)        // 512 matrices
#define PAH 72             // fp16 A pitch (halves) -> 144B rows, conflict-free

// All matrices in reciprocal-exp domain: W = exp(-m), stored fp16 normalized
// per-quarter (max=1) with float scales. log-semiring matmul:
//   out[i,j] = rcp( sum_k rcp( A[i,k] + B[k,j] ) )   (scale-homogeneous)
__device__ float g_p0tab[MAT];         // exp(-p[0]) fp32 (final)

// fp16 normalized storage (+ per-quarter float4 scales)
__device__ uint4 h_buf0_[NMAT * MAT / 8];
__device__ uint4 h_buf1_[NMAT * MAT / 8];
__device__ uint4 h_qtab_[256 * MAT / 8];
__device__ uint4 h_ttab_[16 * MAT / 8];
__device__ uint4 h_wtab_[4 * MAT / 8];
__device__ float4 g_sc0[NMAT];
__device__ float4 g_sc1[NMAT];
__device__ float4 g_scq[256];
__device__ float4 g_sct[16];
__device__ float4 g_scw[4];
#define H_BUF0 ((__half*)h_buf0_)
#define H_BUF1 ((__half*)h_buf1_)
#define H_QTAB ((__half*)h_qtab_)
#define H_TTAB ((__half*)h_ttab_)
#define H_WTAB ((__half*)h_wtab_)

__device__ __forceinline__ float frcp(float x) {
    float r;
    asm("rcp.approx.f32 %0, %1;" : "=f"(r) : "f"(x));
    return r;
}

// Packed fp16x2 reciprocal WITHOUT MUFU: 16-bit magic bit-trick estimate
// (valid for lanes in [0, 2] -- guaranteed by normalization, no cross-lane
// borrow) + 2 Newton steps in residual form. x=0 -> inf (correct limit).
__device__ __forceinline__ __half2 h2rcp_nr(__half2 x) {
    unsigned xi = *reinterpret_cast<unsigned*>(&x);
    unsigned yi = 0x77847784u - xi;
    __half2 y = *reinterpret_cast<__half2*>(&yi);
    const __half2 one = __float2half2_rn(1.f);
    __half2 nx = __hneg2(x);                 // folds into HFMA2 neg modifier
    __half2 e = __hfma2(nx, y, one);
    y = __hfma2(y, e, y);
    e = __hfma2(nx, y, one);
    y = __hfma2(y, e, y);
    return y;
}

__device__ __forceinline__ float sc_comp(float4 s, int q) {
    return (q < 2) ? (q == 0 ? s.x : s.y) : (q == 2 ? s.z : s.w);
}

// ---------------------------------------------------------------------------
// fp16 quarter matmul with fused per-quarter normalization epilogue.
// One CTA = 64x16 output quarter q. scA = A's 4 quarter scales, scB = B's
// scale for quarter q. Writes normalized fp16 + scOut (the q-th scale slot).
// ---------------------------------------------------------------------------
__device__ __forceinline__ void hmm_quarter(const __half* __restrict__ Ah, float4 scA,
                                            const __half* __restrict__ Bh, float scB,
                                            __half* __restrict__ Dst,
                                            float* __restrict__ scOut, int q) {
    __shared__ __align__(16) __half sA[D * PAH];
    __shared__ __align__(16) __half sB[D * 16];
    __shared__ float wred[8];
    const int t = threadIdx.x;

    float s = fmaxf(fmaxf(fmaxf(scA.x, scA.y), fmaxf(scA.z, scA.w)), scB);
    float invs = 1.f / s;
    __half2 rB = __float2half2_rn(scB * invs);
    float rAf0 = scA.x * invs, rAf1 = scA.y * invs;
    float rAf2 = scA.z * invs, rAf3 = scA.w * invs;

    // stage A: 512 uint4 (8 halves each); quarter of columns = (c8>>1)
#pragma unroll
    for (int i = 0; i < 2; i++) {
        int id = t + i * 256;
        int r = id >> 3, c8 = id & 7;
        int qa = c8 >> 1;
        float rf = (qa < 2) ? (qa == 0 ? rAf0 : rAf1) : (qa == 2 ? rAf2 : rAf3);
        __half2 rA = __float2half2_rn(rf);
        uint4 v = ((const uint4*)Ah)[id];
        __half2* hv = (__half2*)&v;
        hv[0] = __hmul2(hv[0], rA); hv[1] = __hmul2(hv[1], rA);
        hv[2] = __hmul2(hv[2], rA); hv[3] = __hmul2(hv[3], rA);
        *(uint4*)&sA[r * PAH + c8 * 8] = v;
    }
    // stage B quarter: 128 uint4
    if (t < 128) {
        int r = t >> 1, c8 = t & 1;
        uint4 v = *(const uint4*)&Bh[r * D + q * 16 + c8 * 8];
        __half2* hv = (__half2*)&v;
        hv[0] = __hmul2(hv[0], rB); hv[1] = __hmul2(hv[1], rB);
        hv[2] = __hmul2(hv[2], rB); hv[3] = __hmul2(hv[3], rB);
        *(uint4*)&sB[r * 16 + c8 * 8] = v;
    }
    __syncthreads();

    const int row = t >> 2, cg = t & 3;
    const __half* ap = &sA[row * PAH];
    const __half* bp = &sB[cg * 4];
    const __half2 hz = __float2half2_rn(0.f);
    __half2 acc01[8], acc23[8];
#pragma unroll
    for (int i = 0; i < 8; i++) { acc01[i] = hz; acc23[i] = hz; }

#pragma unroll
    for (int k8 = 0; k8 < 8; k8++) {
        uint4 a8 = *(const uint4*)&ap[k8 * 8];
        const __half2* ah = (const __half2*)&a8;
#pragma unroll
        for (int kk = 0; kk < 4; kk++) {
            int k0 = k8 * 8 + kk * 2;
            __half2 alo = __low2half2(ah[kk]);
            __half2 ahi = __high2half2(ah[kk]);
            int pi = kk * 2;
            uint2 b0 = *(const uint2*)&bp[k0 * 16];
            __half2 b01 = *(__half2*)&b0.x, b23 = *(__half2*)&b0.y;
            acc01[pi] = __hadd2(acc01[pi], h2rcp_nr(__hadd2(alo, b01)));
            acc23[pi] = __hadd2(acc23[pi], h2rcp_nr(__hadd2(alo, b23)));
            uint2 b1 = *(const uint2*)&bp[(k0 + 1) * 16];
            __half2 c01 = *(__half2*)&b1.x, c23 = *(__half2*)&b1.y;
            acc01[pi + 1] = __hadd2(acc01[pi + 1], h2rcp_nr(__hadd2(ahi, c01)));
            acc23[pi + 1] = __hadd2(acc23[pi + 1], h2rcp_nr(__hadd2(ahi, c23)));
        }
    }

    float s0 = 0.f, s1 = 0.f, s2 = 0.f, s3 = 0.f;
#pragma unroll
    for (int i = 0; i < 8; i++) {
        float2 f01 = __half22float2(acc01[i]);
        float2 f23 = __half22float2(acc23[i]);
        s0 += f01.x; s1 += f01.y; s2 += f23.x; s3 += f23.y;
    }
    float o0 = frcp(s0), o1 = frcp(s1), o2 = frcp(s2), o3 = frcp(s3);

    // fused per-quarter max reduction + normalized fp16 store
    float m = fmaxf(fmaxf(o0, o1), fmaxf(o2, o3));
#pragma unroll
    for (int off = 16; off; off >>= 1)
        m = fmaxf(m, __shfl_xor_sync(0xffffffffu, m, off));
    if ((t & 31) == 0) wred[t >> 5] = m;
    __syncthreads();
    float mx = wred[0];
#pragma unroll
    for (int i = 1; i < 8; i++) mx = fmaxf(mx, wred[i]);
    float inv = (mx > 0.f) ? frcp(mx) : 0.f;

    __half2 h0 = __floats2half2_rn(o0 * inv, o1 * inv);
    __half2 h1 = __floats2half2_rn(o2 * inv, o3 * inv);
    uint2 u;
    u.x = *(unsigned*)&h0;
    u.y = *(unsigned*)&h1;
    *(uint2*)&Dst[row * D + q * 16 + cg * 4] = u;
    if (t == 0) *scOut = s * mx;
}

// ---------------------------------------------------------------------------
// Resolver: value of index m before pass 2^slog lives at level
// p = min(floor(log2 m), slog-1).
// ---------------------------------------------------------------------------
struct HMat { const __half* m; float4 sc; };

__device__ __forceinline__ int quad_idx(const int* __restrict__ act, int b, int m) {
    const int* a = act + b * L + (m - 3);
    return ((a[0] * 4 + a[1]) * 4 + a[2]) * 4 + a[3];
}

__device__ __forceinline__ HMat latest_h(const int* __restrict__ act,
                                         int b, int m, int slog) {
    int slot = b * L + m;
    size_t off = (size_t)slot * MAT;
    HMat r;
    if (m < 2) { r.m = H_BUF0 + off; r.sc = g_sc0[slot]; return r; }
    int p = 31 - __clz(m);
    if (p > slog - 1) p = slog - 1;
    if (p == 1) {
        if (m == 2) { r.m = H_BUF1 + off; r.sc = g_sc1[slot]; return r; }
        int idx = quad_idx(act, b, m);
        r.m = H_QTAB + (size_t)idx * MAT; r.sc = g_scq[idx]; return r;
    }
    if (p & 1) { r.m = H_BUF1 + off; r.sc = g_sc1[slot]; }
    else       { r.m = H_BUF0 + off; r.sc = g_sc0[slot]; }
    return r;
}

// ---------------------------------------------------------------------------
// exp tables: a==0 -> p0tab fp32. a>=1 -> wtab fp16 normalized + scale.
// ---------------------------------------------------------------------------
__global__ void exp_tab_kernel(const float* __restrict__ p) {
    int a = blockIdx.x;
    __shared__ float wred[8];
    int t = threadIdx.x;  // 256
    const float4* src = (const float4*)(p + (size_t)a * MAT);
    float4 v[4];
    float m = 0.f;
#pragma unroll
    for (int i = 0; i < 4; i++) {
        float4 x = src[t + i * 256];
        v[i] = make_float4(expf(-x.x), expf(-x.y), expf(-x.z), expf(-x.w));
        m = fmaxf(m, fmaxf(fmaxf(v[i].x, v[i].y), fmaxf(v[i].z, v[i].w)));
    }
    if (a == 0) {
#pragma unroll
        for (int i = 0; i < 4; i++) ((float4*)g_p0tab)[t + i * 256] = v[i];
        return;
    }
#pragma unroll
    for (int off = 16; off; off >>= 1)
        m = fmaxf(m, __shfl_xor_sync(0xffffffffu, m, off));
    if ((t & 31) == 0) wred[t >> 5] = m;
    __syncthreads();
    float mx = wred[0];
#pragma unroll
    for (int i = 1; i < 8; i++) mx = fmaxf(mx, wred[i]);
    float inv = (mx > 0.f) ? 1.f / mx : 0.f;
    __half* hdst = H_WTAB + (size_t)(a - 1) * MAT;
#pragma unroll
    for (int i = 0; i < 4; i++) {
        __half2 h0 = __floats2half2_rn(v[i].x * inv, v[i].y * inv);
        __half2 h1 = __floats2half2_rn(v[i].z * inv, v[i].w * inv);
        uint2 u; u.x = *(unsigned*)&h0; u.y = *(unsigned*)&h1;
        ((uint2*)hdst)[t + i * 256] = u;
    }
    if (t == 0) g_scw[a - 1] = make_float4(mx, mx, mx, mx);
}

// pair products fp16: 16 pairs x 4 quarters = 64 CTAs
__global__ void __launch_bounds__(256, 6) pairh_kernel() {
    int pidx = blockIdx.x >> 2, q = blockIdx.x & 3;
    int a = pidx >> 2, b = pidx & 3;
    hmm_quarter(H_WTAB + (size_t)a * MAT, g_scw[a],
                H_WTAB + (size_t)b * MAT, sc_comp(g_scw[b], q),
                H_TTAB + (size_t)pidx * MAT, (float*)&g_sct[pidx] + q, q);
}

// quads (1024) + tris (32) + base fp16 copies l=0,1 (16) = 1072 CTAs
__global__ void __launch_bounds__(256, 6) stage2h_kernel(const int* __restrict__ act) {
    int bid = blockIdx.x;
    if (bid < 1024) {
        int qidx = bid >> 2, q = bid & 3;
        int hi = qidx >> 4, lo = qidx & 15;
        hmm_quarter(H_TTAB + (size_t)hi * MAT, g_sct[hi],
                    H_TTAB + (size_t)lo * MAT, sc_comp(g_sct[lo], q),
                    H_QTAB + (size_t)qidx * MAT, (float*)&g_scq[qidx] + q, q);
    } else if (bid < 1056) {
        int i = bid - 1024;
        int b = i >> 2, q = i & 3;
        int a0 = act[b * L], a12 = act[b * L + 1] * 4 + act[b * L + 2];
        int slot = b * L + 2;
        hmm_quarter(H_WTAB + (size_t)a0 * MAT, g_scw[a0],
                    H_TTAB + (size_t)a12 * MAT, sc_comp(g_sct[a12], q),
                    H_BUF1 + (size_t)slot * MAT, (float*)&g_sc1[slot] + q, q);
    } else {
        int i = bid - 1056;                 // 0..15
        int b = i >> 1, which = i & 1;      // l = 0 or 1
        int slot = b * L + which;
        const uint4* src;
        float4 sc;
        if (which) {
            int pidx = act[b * L] * 4 + act[b * L + 1];
            src = (const uint4*)(H_TTAB + (size_t)pidx * MAT);
            sc = g_sct[pidx];
        } else {
            int a0 = act[b * L];
            src = (const uint4*)(H_WTAB + (size_t)a0 * MAT);
            sc = g_scw[a0];
        }
        uint4* dst = (uint4*)(H_BUF0 + (size_t)slot * MAT);
        for (int j = threadIdx.x; j < MAT / 8; j += 256) dst[j] = src[j];
        if (threadIdx.x == 0) g_sc0[slot] = sc;
    }
}

// Doubling pass for step = 2^slog (slog >= 2). Fully fp16, fused normalize.
__global__ void __launch_bounds__(256, 6) hstep_kernel(const int* __restrict__ act,
                                                       int slog) {
    int step = 1 << slog, n = L - step;
    int idx = blockIdx.x >> 2, q = blockIdx.x & 3;
    int b = idx / n;
    int l = step + (idx - b * n);
    HMat A = latest_h(act, b, l - step, slog);
    HMat Bm = latest_h(act, b, l, slog);
    int slot = b * L + l;
    __half* dst = ((slog & 1) ? H_BUF1 : H_BUF0) + (size_t)slot * MAT;
    float* scarr = (float*)(((slog & 1) ? g_sc1 : g_sc0) + slot) + q;
    hmm_quarter(A.m, A.sc, Bm.m, sc_comp(Bm.sc, q), dst, scarr, q);
}

// Final: x = init (x) PM ; y = x (x) p0 ; output in log domain.
__global__ void final_kernel(const int* __restrict__ act,
                             const float* __restrict__ init_vec,
                             float* __restrict__ out) {
    int bl = blockIdx.x;
    int b = bl >> 6, l = bl & 63;
    HMat W = latest_h(act, b, l, 6);
    __shared__ float ci[D];
    __shared__ float xw[D];
    int t = threadIdx.x;   // 64
    ci[t] = expf(-init_vec[t]);
    __syncthreads();

    float scq = sc_comp(W.sc, t >> 4);
    float s = 0.f;
#pragma unroll 8
    for (int k = 0; k < D; k++)
        s += frcp(fmaf(scq, __half2float(W.m[k * D + t]), ci[k]));
    xw[t] = frcp(s);
    __syncthreads();

    float s2 = 0.f;
#pragma unroll 8
    for (int k = 0; k < D; k++)
        s2 += frcp(xw[k] + g_p0tab[k * D + t]);
    out[(size_t)bl * D + t] = logf(s2);
}

extern "C" void kernel_launch(void* const* d_in, const int* in_sizes, int n_in,
                              void* d_out, int out_size) {
    const float* p        = (const float*)d_in[0];  // (5, 64, 64)
    const float* init_vec = (const float*)d_in[1];  // (64,)
    const int*   act      = (const int*)d_in[2];    // (8, 64)
    float* out = (float*)d_out;                     // (8, 64, 64)

    exp_tab_kernel<<<5, 256>>>(p);
    pairh_kernel<<<64, 256>>>();
    stage2h_kernel<<<1072, 256>>>(act);
    hstep_kernel<<<8 * (L - 4)  * 4, 256>>>(act, 2);   // -> H_BUF0
    hstep_kernel<<<8 * (L - 8)  * 4, 256>>>(act, 3);   // -> H_BUF1
    hstep_kernel<<<8 * (L - 16) * 4, 256>>>(act, 4);   // -> H_BUF0
    hstep_kernel<<<8 * (L - 32) * 4, 256>>>(act, 5);   // -> H_BUF1
    final_kernel<<<512, 64>>>(act, init_vec, out);
}

// round 14
// speedup vs baseline: 1.3435x; 1.1257x over previous
#include <cuda_runtime.h>
#include <cuda_fp16.h>

#define D 64
#define L 64
#define BB 8
#define MAT (D*D)          // 4096 elems per matrix
#define NMAT (BB*L)        // 512 matrices
#define PAH 72             // fp16 A pitch (halves) -> 144B rows, conflict-free

// All matrices in reciprocal-exp domain: W = exp(-m), stored fp16 normalized
// per-quarter (max=1) with float scales. log-semiring matmul:
//   out[i,j] = rcp( sum_k rcp( A[i,k] + B[k,j] ) )   (scale-homogeneous)
__device__ float g_p0tab[MAT];         // exp(-p[0]) fp32 (final)

// fp16 normalized storage (+ per-quarter float4 scales)
__device__ uint4 h_buf0_[NMAT * MAT / 8];
__device__ uint4 h_buf1_[NMAT * MAT / 8];
__device__ uint4 h_qtab_[256 * MAT / 8];
__device__ uint4 h_ttab_[16 * MAT / 8];
__device__ uint4 h_wtab_[4 * MAT / 8];
__device__ float4 g_sc0[NMAT];
__device__ float4 g_sc1[NMAT];
__device__ float4 g_scq[256];
__device__ float4 g_sct[16];
__device__ float4 g_scw[4];
#define H_BUF0 ((__half*)h_buf0_)
#define H_BUF1 ((__half*)h_buf1_)
#define H_QTAB ((__half*)h_qtab_)
#define H_TTAB ((__half*)h_ttab_)
#define H_WTAB ((__half*)h_wtab_)

__device__ __forceinline__ float frcp(float x) {
    float r;
    asm("rcp.approx.f32 %0, %1;" : "=f"(r) : "f"(x));
    return r;
}

// Packed fp16x2 reciprocal WITHOUT MUFU: 16-bit magic bit-trick estimate
// (valid for lanes in [0, 2] -- guaranteed by normalization, no cross-lane
// borrow) + ONE Halley step (cubic): residual e0^3 ~ 4e-5 < fp16 eps.
// x=0 -> inf (correct semiring limit).
__device__ __forceinline__ __half2 h2rcp_nr(__half2 x) {
    unsigned xi = *reinterpret_cast<unsigned*>(&x);
    unsigned yi = 0x77847784u - xi;
    __half2 y = *reinterpret_cast<__half2*>(&yi);
    const __half2 one = __float2half2_rn(1.f);
    __half2 nx = __hneg2(x);                 // folds into HFMA2 neg modifier
    __half2 e = __hfma2(nx, y, one);         // e = 1 - x*y
    __half2 t = __hfma2(e, e, e);            // t = e + e^2
    y = __hfma2(y, t, y);                    // y *= 1 + e + e^2
    return y;
}

__device__ __forceinline__ float sc_comp(float4 s, int q) {
    return (q < 2) ? (q == 0 ? s.x : s.y) : (q == 2 ? s.z : s.w);
}

// ---------------------------------------------------------------------------
// fp16 quarter matmul with fused per-quarter normalization epilogue.
// One CTA = 64x16 output quarter q. scA = A's 4 quarter scales, scB = B's
// scale for quarter q. Writes normalized fp16 + scOut (the q-th scale slot).
// ---------------------------------------------------------------------------
__device__ __forceinline__ void hmm_quarter(const __half* __restrict__ Ah, float4 scA,
                                            const __half* __restrict__ Bh, float scB,
                                            __half* __restrict__ Dst,
                                            float* __restrict__ scOut, int q) {
    __shared__ __align__(16) __half sA[D * PAH];
    __shared__ __align__(16) __half sB[D * 16];
    __shared__ float wred[8];
    const int t = threadIdx.x;

    float s = fmaxf(fmaxf(fmaxf(scA.x, scA.y), fmaxf(scA.z, scA.w)), scB);
    float invs = 1.f / s;
    __half2 rB = __float2half2_rn(scB * invs);
    float rAf0 = scA.x * invs, rAf1 = scA.y * invs;
    float rAf2 = scA.z * invs, rAf3 = scA.w * invs;

    // stage A: 512 uint4 (8 halves each); quarter of columns = (c8>>1)
#pragma unroll
    for (int i = 0; i < 2; i++) {
        int id = t + i * 256;
        int r = id >> 3, c8 = id & 7;
        int qa = c8 >> 1;
        float rf = (qa < 2) ? (qa == 0 ? rAf0 : rAf1) : (qa == 2 ? rAf2 : rAf3);
        __half2 rA = __float2half2_rn(rf);
        uint4 v = ((const uint4*)Ah)[id];
        __half2* hv = (__half2*)&v;
        hv[0] = __hmul2(hv[0], rA); hv[1] = __hmul2(hv[1], rA);
        hv[2] = __hmul2(hv[2], rA); hv[3] = __hmul2(hv[3], rA);
        *(uint4*)&sA[r * PAH + c8 * 8] = v;
    }
    // stage B quarter: 128 uint4
    if (t < 128) {
        int r = t >> 1, c8 = t & 1;
        uint4 v = *(const uint4*)&Bh[r * D + q * 16 + c8 * 8];
        __half2* hv = (__half2*)&v;
        hv[0] = __hmul2(hv[0], rB); hv[1] = __hmul2(hv[1], rB);
        hv[2] = __hmul2(hv[2], rB); hv[3] = __hmul2(hv[3], rB);
        *(uint4*)&sB[r * 16 + c8 * 8] = v;
    }
    __syncthreads();

    const int row = t >> 2, cg = t & 3;
    const __half* ap = &sA[row * PAH];
    const __half* bp = &sB[cg * 4];
    const __half2 hz = __float2half2_rn(0.f);
    __half2 acc01[8], acc23[8];
#pragma unroll
    for (int i = 0; i < 8; i++) { acc01[i] = hz; acc23[i] = hz; }

#pragma unroll
    for (int k8 = 0; k8 < 8; k8++) {
        uint4 a8 = *(const uint4*)&ap[k8 * 8];
        const __half2* ah = (const __half2*)&a8;
#pragma unroll
        for (int kk = 0; kk < 4; kk++) {
            int k0 = k8 * 8 + kk * 2;
            __half2 alo = __low2half2(ah[kk]);
            __half2 ahi = __high2half2(ah[kk]);
            int pi = kk * 2;
            uint2 b0 = *(const uint2*)&bp[k0 * 16];
            __half2 b01 = *(__half2*)&b0.x, b23 = *(__half2*)&b0.y;
            acc01[pi] = __hadd2(acc01[pi], h2rcp_nr(__hadd2(alo, b01)));
            acc23[pi] = __hadd2(acc23[pi], h2rcp_nr(__hadd2(alo, b23)));
            uint2 b1 = *(const uint2*)&bp[(k0 + 1) * 16];
            __half2 c01 = *(__half2*)&b1.x, c23 = *(__half2*)&b1.y;
            acc01[pi + 1] = __hadd2(acc01[pi + 1], h2rcp_nr(__hadd2(ahi, c01)));
            acc23[pi + 1] = __hadd2(acc23[pi + 1], h2rcp_nr(__hadd2(ahi, c23)));
        }
    }

    float s0 = 0.f, s1 = 0.f, s2 = 0.f, s3 = 0.f;
#pragma unroll
    for (int i = 0; i < 8; i++) {
        float2 f01 = __half22float2(acc01[i]);
        float2 f23 = __half22float2(acc23[i]);
        s0 += f01.x; s1 += f01.y; s2 += f23.x; s3 += f23.y;
    }
    float o0 = frcp(s0), o1 = frcp(s1), o2 = frcp(s2), o3 = frcp(s3);

    // fused per-quarter max reduction + normalized fp16 store
    float m = fmaxf(fmaxf(o0, o1), fmaxf(o2, o3));
#pragma unroll
    for (int off = 16; off; off >>= 1)
        m = fmaxf(m, __shfl_xor_sync(0xffffffffu, m, off));
    if ((t & 31) == 0) wred[t >> 5] = m;
    __syncthreads();
    float mx = wred[0];
#pragma unroll
    for (int i = 1; i < 8; i++) mx = fmaxf(mx, wred[i]);
    float inv = (mx > 0.f) ? frcp(mx) : 0.f;

    __half2 h0 = __floats2half2_rn(o0 * inv, o1 * inv);
    __half2 h1 = __floats2half2_rn(o2 * inv, o3 * inv);
    uint2 u;
    u.x = *(unsigned*)&h0;
    u.y = *(unsigned*)&h1;
    *(uint2*)&Dst[row * D + q * 16 + cg * 4] = u;
    if (t == 0) *scOut = s * mx;
}

// ---------------------------------------------------------------------------
// Resolver: value of index m before pass 2^slog lives at level
// p = min(floor(log2 m), slog-1).
// ---------------------------------------------------------------------------
struct HMat { const __half* m; float4 sc; };

__device__ __forceinline__ int quad_idx(const int* __restrict__ act, int b, int m) {
    const int* a = act + b * L + (m - 3);
    return ((a[0] * 4 + a[1]) * 4 + a[2]) * 4 + a[3];
}

__device__ __forceinline__ HMat latest_h(const int* __restrict__ act,
                                         int b, int m, int slog) {
    int slot = b * L + m;
    size_t off = (size_t)slot * MAT;
    HMat r;
    if (m < 2) { r.m = H_BUF0 + off; r.sc = g_sc0[slot]; return r; }
    int p = 31 - __clz(m);
    if (p > slog - 1) p = slog - 1;
    if (p == 1) {
        if (m == 2) { r.m = H_BUF1 + off; r.sc = g_sc1[slot]; return r; }
        int idx = quad_idx(act, b, m);
        r.m = H_QTAB + (size_t)idx * MAT; r.sc = g_scq[idx]; return r;
    }
    if (p & 1) { r.m = H_BUF1 + off; r.sc = g_sc1[slot]; }
    else       { r.m = H_BUF0 + off; r.sc = g_sc0[slot]; }
    return r;
}

// ---------------------------------------------------------------------------
// exp tables: a==0 -> p0tab fp32. a>=1 -> wtab fp16 normalized + scale.
// ---------------------------------------------------------------------------
__global__ void exp_tab_kernel(const float* __restrict__ p) {
    int a = blockIdx.x;
    __shared__ float wred[8];
    int t = threadIdx.x;  // 256
    const float4* src = (const float4*)(p + (size_t)a * MAT);
    float4 v[4];
    float m = 0.f;
#pragma unroll
    for (int i = 0; i < 4; i++) {
        float4 x = src[t + i * 256];
        v[i] = make_float4(expf(-x.x), expf(-x.y), expf(-x.z), expf(-x.w));
        m = fmaxf(m, fmaxf(fmaxf(v[i].x, v[i].y), fmaxf(v[i].z, v[i].w)));
    }
    if (a == 0) {
#pragma unroll
        for (int i = 0; i < 4; i++) ((float4*)g_p0tab)[t + i * 256] = v[i];
        return;
    }
#pragma unroll
    for (int off = 16; off; off >>= 1)
        m = fmaxf(m, __shfl_xor_sync(0xffffffffu, m, off));
    if ((t & 31) == 0) wred[t >> 5] = m;
    __syncthreads();
    float mx = wred[0];
#pragma unroll
    for (int i = 1; i < 8; i++) mx = fmaxf(mx, wred[i]);
    float inv = (mx > 0.f) ? 1.f / mx : 0.f;
    __half* hdst = H_WTAB + (size_t)(a - 1) * MAT;
#pragma unroll
    for (int i = 0; i < 4; i++) {
        __half2 h0 = __floats2half2_rn(v[i].x * inv, v[i].y * inv);
        __half2 h1 = __floats2half2_rn(v[i].z * inv, v[i].w * inv);
        uint2 u; u.x = *(unsigned*)&h0; u.y = *(unsigned*)&h1;
        ((uint2*)hdst)[t + i * 256] = u;
    }
    if (t == 0) g_scw[a - 1] = make_float4(mx, mx, mx, mx);
}

// pair products fp16: 16 pairs x 4 quarters = 64 CTAs
__global__ void __launch_bounds__(256, 6) pairh_kernel() {
    int pidx = blockIdx.x >> 2, q = blockIdx.x & 3;
    int a = pidx >> 2, b = pidx & 3;
    hmm_quarter(H_WTAB + (size_t)a * MAT, g_scw[a],
                H_WTAB + (size_t)b * MAT, sc_comp(g_scw[b], q),
                H_TTAB + (size_t)pidx * MAT, (float*)&g_sct[pidx] + q, q);
}

// quads (1024) + tris (32) + base fp16 copies l=0,1 (16) = 1072 CTAs
__global__ void __launch_bounds__(256, 6) stage2h_kernel(const int* __restrict__ act) {
    int bid = blockIdx.x;
    if (bid < 1024) {
        int qidx = bid >> 2, q = bid & 3;
        int hi = qidx >> 4, lo = qidx & 15;
        hmm_quarter(H_TTAB + (size_t)hi * MAT, g_sct[hi],
                    H_TTAB + (size_t)lo * MAT, sc_comp(g_sct[lo], q),
                    H_QTAB + (size_t)qidx * MAT, (float*)&g_scq[qidx] + q, q);
    } else if (bid < 1056) {
        int i = bid - 1024;
        int b = i >> 2, q = i & 3;
        int a0 = act[b * L], a12 = act[b * L + 1] * 4 + act[b * L + 2];
        int slot = b * L + 2;
        hmm_quarter(H_WTAB + (size_t)a0 * MAT, g_scw[a0],
                    H_TTAB + (size_t)a12 * MAT, sc_comp(g_sct[a12], q),
                    H_BUF1 + (size_t)slot * MAT, (float*)&g_sc1[slot] + q, q);
    } else {
        int i = bid - 1056;                 // 0..15
        int b = i >> 1, which = i & 1;      // l = 0 or 1
        int slot = b * L + which;
        const uint4* src;
        float4 sc;
        if (which) {
            int pidx = act[b * L] * 4 + act[b * L + 1];
            src = (const uint4*)(H_TTAB + (size_t)pidx * MAT);
            sc = g_sct[pidx];
        } else {
            int a0 = act[b * L];
            src = (const uint4*)(H_WTAB + (size_t)a0 * MAT);
            sc = g_scw[a0];
        }
        uint4* dst = (uint4*)(H_BUF0 + (size_t)slot * MAT);
        for (int j = threadIdx.x; j < MAT / 8; j += 256) dst[j] = src[j];
        if (threadIdx.x == 0) g_sc0[slot] = sc;
    }
}

// Doubling pass for step = 2^slog (slog >= 2). Fully fp16, fused normalize.
__global__ void __launch_bounds__(256, 6) hstep_kernel(const int* __restrict__ act,
                                                       int slog) {
    int step = 1 << slog, n = L - step;
    int idx = blockIdx.x >> 2, q = blockIdx.x & 3;
    int b = idx / n;
    int l = step + (idx - b * n);
    HMat A = latest_h(act, b, l - step, slog);
    HMat Bm = latest_h(act, b, l, slog);
    int slot = b * L + l;
    __half* dst = ((slog & 1) ? H_BUF1 : H_BUF0) + (size_t)slot * MAT;
    float* scarr = (float*)(((slog & 1) ? g_sc1 : g_sc0) + slot) + q;
    hmm_quarter(A.m, A.sc, Bm.m, sc_comp(Bm.sc, q), dst, scarr, q);
}

// Final: x = init (x) PM ; y = x (x) p0 ; output in log domain.
__global__ void final_kernel(const int* __restrict__ act,
                             const float* __restrict__ init_vec,
                             float* __restrict__ out) {
    int bl = blockIdx.x;
    int b = bl >> 6, l = bl & 63;
    HMat W = latest_h(act, b, l, 6);
    __shared__ float ci[D];
    __shared__ float xw[D];
    int t = threadIdx.x;   // 64
    ci[t] = expf(-init_vec[t]);
    __syncthreads();

    float scq = sc_comp(W.sc, t >> 4);
    float s = 0.f;
#pragma unroll 8
    for (int k = 0; k < D; k++)
        s += frcp(fmaf(scq, __half2float(W.m[k * D + t]), ci[k]));
    xw[t] = frcp(s);
    __syncthreads();

    float s2 = 0.f;
#pragma unroll 8
    for (int k = 0; k < D; k++)
        s2 += frcp(xw[k] + g_p0tab[k * D + t]);
    out[(size_t)bl * D + t] = logf(s2);
}

extern "C" void kernel_launch(void* const* d_in, const int* in_sizes, int n_in,
                              void* d_out, int out_size) {
    const float* p        = (const float*)d_in[0];  // (5, 64, 64)
    const float* init_vec = (const float*)d_in[1];  // (64,)
    const int*   act      = (const int*)d_in[2];    // (8, 64)
    float* out = (float*)d_out;                     // (8, 64, 64)

    exp_tab_kernel<<<5, 256>>>(p);
    pairh_kernel<<<64, 256>>>();
    stage2h_kernel<<<1072, 256>>>(act);
    hstep_kernel<<<8 * (L - 4)  * 4, 256>>>(act, 2);   // -> H_BUF0
    hstep_kernel<<<8 * (L - 8)  * 4, 256>>>(act, 3);   // -> H_BUF1
    hstep_kernel<<<8 * (L - 16) * 4, 256>>>(act, 4);   // -> H_BUF0
    hstep_kernel<<<8 * (L - 32) * 4, 256>>>(act, 5);   // -> H_BUF1
    final_kernel<<<512, 64>>>(act, init_vec, out);
}